// round 1
// baseline (speedup 1.0000x reference)
#include <cuda_runtime.h>
#include <cuda_bf16.h>

// GoalDecoderLSTM: B=131072, H=64, E=16, G=32, SEQ=30
// Folded formulation:
//   gates = Wcat(80x256, gate-interleaved) @ [h;x]  + bcat
//   c' = sig(f)*c + sig(i)*tanh(g);  h' = sig(o)*tanh(c')
//   rel = W2(2x64)@h' + M2(2x2)@abs + goalc(2) + cvec(2)
//   abs += rel;  x' = leaky_relu(W_se(16x2)@rel + b_se)
// goalc = Mg(2x64)@goals_flat + cg   (precomputed per element at tile init)

#define HDIM    64
#define KDIM    80
#define NG      256
#define TB      128
#define TBP     132           // padded SMEM row (conflict-free, 16B aligned)
#define SEQ     30
#define NTHR    256

// ---- SMEM layout (floats) ----
#define OFF_W     0                        // 80*256 = 20480
#define OFF_A     (OFF_W + 80*256)         // 2*80*132 = 21120 (double-buffered [h|x])
#define OFF_C     (OFF_A + 2*80*TBP)       // 64*132 = 8448
#define OFF_BC    (OFF_C + 64*TBP)         // 256
#define OFF_W2    (OFF_BC + 256)           // 128
#define OFF_MG    (OFF_W2 + 128)           // 128
#define OFF_M2    (OFF_MG + 128)           // 4
#define OFF_CV    (OFF_M2 + 4)             // 2
#define OFF_CG    (OFF_CV + 2)             // 2
#define OFF_WSE   (OFF_CG + 2)             // 32
#define OFF_BSE   (OFF_WSE + 32)           // 16
#define OFF_REL   (OFF_BSE + 16)           // 256
#define OFF_ABS   (OFF_REL + 256)          // 256
#define OFF_GOALC (OFF_ABS + 256)          // 256
#define SMEM_FLOATS (OFF_GOALC + 256)
#define SMEM_BYTES  (SMEM_FLOATS * 4)      // 205,536 B < 227 KB

// ---- device scratch (prep -> main) ----
__device__ float g_Wcat[80 * 256];
__device__ float g_bcat[256];
__device__ float g_W2[128];
__device__ float g_Mg[128];
__device__ float g_M2[4];
__device__ float g_cvec[2];
__device__ float g_cg[2];

// ---- f32x2 packed helpers (Blackwell FFMA2) ----
typedef unsigned long long u64;

__device__ __forceinline__ u64 pack2(float x) {
    u64 r; asm("mov.b64 %0, {%1, %1};" : "=l"(r) : "f"(x)); return r;
}
__device__ __forceinline__ float2 unpack2(u64 v) {
    float2 r; asm("mov.b64 {%0, %1}, %2;" : "=f"(r.x), "=f"(r.y) : "l"(v)); return r;
}
__device__ __forceinline__ void ffma2(u64& acc, u64 a, u64 b) {
    asm("fma.rn.f32x2 %0, %1, %2, %0;" : "+l"(acc) : "l"(a), "l"(b));
}

__device__ __forceinline__ float sigf(float x) {
    return __fdividef(1.0f, 1.0f + __expf(-x));
}
__device__ __forceinline__ float tanh_fast(float x) {
    float ax = fabsf(x);
    float e  = __expf(-2.0f * ax);
    float t  = __fdividef(1.0f - e, 1.0f + e);
    return copysignf(t, x);
}

// ============================================================================
// Prep kernel: fold small matrices, interleave gate weights
// ============================================================================
__global__ void prep_kernel(const float* __restrict__ W_ih, const float* __restrict__ W_hh,
                            const float* __restrict__ b_ih, const float* __restrict__ b_hh,
                            const float* __restrict__ W_h2p, const float* __restrict__ b_h2p,
                            const float* __restrict__ W_goal, const float* __restrict__ b_goal,
                            const float* __restrict__ W_abs, const float* __restrict__ b_abs)
{
    int tid = threadIdx.x;

    // Wcat[k][4j+t]: k<64 -> W_hh[t*64+j][k], k>=64 -> W_ih[t*64+j][k-64]
    for (int idx = tid; idx < 80 * 256; idx += NTHR) {
        int k = idx >> 8, gg = idx & 255;
        int j = gg >> 2, t = gg & 3;
        int row = t * 64 + j;
        g_Wcat[idx] = (k < 64) ? W_hh[row * 64 + k] : W_ih[row * 16 + (k - 64)];
    }
    {
        int j = tid >> 2, t = tid & 3, row = t * 64 + j;
        g_bcat[tid] = b_ih[row] + b_hh[row];
    }
    if (tid < 128) {
        int r = tid >> 6, j = tid & 63;
        g_W2[tid] = W_h2p[r * 192 + j];
        float s = 0.f;
        for (int m = 0; m < 64; m++) s += W_h2p[r * 192 + 128 + m] * W_goal[m * 64 + j];
        g_Mg[tid] = s;
    }
    if (tid < 4) {
        int r = tid >> 1, c = tid & 1;
        float s = 0.f;
        for (int m = 0; m < 64; m++) s += W_h2p[r * 192 + 64 + m] * W_abs[m * 2 + c];
        g_M2[tid] = s;
    }
    if (tid < 2) {
        float s = b_h2p[tid];
        for (int m = 0; m < 64; m++) s += W_h2p[tid * 192 + 64 + m] * b_abs[m];
        g_cvec[tid] = s;
        float s2 = 0.f;
        for (int m = 0; m < 64; m++) s2 += W_h2p[tid * 192 + 128 + m] * b_goal[m];
        g_cg[tid] = s2;
    }
}

// ============================================================================
// Main kernel: one CTA per 128-element tile, 30 steps, state in SMEM
// ============================================================================
__global__ void __launch_bounds__(NTHR, 1)
lstm_main(const float* __restrict__ traj_abs, const float* __restrict__ traj_rel,
          const float* __restrict__ h0, const float* __restrict__ c0,
          const float* __restrict__ goals,
          const float* __restrict__ Wse, const float* __restrict__ bse,
          float* __restrict__ out, int B)
{
    extern __shared__ __align__(16) float sm[];
    const int tid = threadIdx.x;
    const int b0 = blockIdx.x * TB;

    // ---- Phase 1: load weights & tile state into SMEM ----
    {
        const float4* src = (const float4*)g_Wcat;
        float4* dst = (float4*)(sm + OFF_W);
        for (int i = tid; i < 80 * 256 / 4; i += NTHR) dst[i] = src[i];
    }
    for (int i = tid; i < 256; i += NTHR) sm[OFF_BC + i] = g_bcat[i];
    for (int i = tid; i < 128; i += NTHR) { sm[OFF_W2 + i] = g_W2[i]; sm[OFF_MG + i] = g_Mg[i]; }
    if (tid < 4)  sm[OFF_M2 + tid] = g_M2[tid];
    if (tid < 2)  { sm[OFF_CV + tid] = g_cvec[tid]; sm[OFF_CG + tid] = g_cg[tid]; }
    if (tid < 32) sm[OFF_WSE + tid] = Wse[tid];
    if (tid < 16) sm[OFF_BSE + tid] = bse[tid];

    // h0 / c0: global-coalesced read, transposed SMEM write (padded rows -> mild conflicts, init only)
    {
        const size_t gbase = (size_t)b0 * HDIM;
        for (int idx = tid; idx < TB * HDIM; idx += NTHR) {
            int e = idx >> 6, j = idx & 63;
            sm[OFF_A + j * TBP + e] = h0[gbase + idx];
            sm[OFF_C + j * TBP + e] = c0[gbase + idx];
        }
    }
    __syncthreads();

    // ---- Phase 2: per-element derived state ----
    {
        int e = tid >> 1, r = tid & 1;
        const float* gp = goals + (size_t)(b0 + e) * 64;
        float s = sm[OFF_CG + r];
        #pragma unroll 8
        for (int q = 0; q < 64; q++) s += sm[OFF_MG + r * 64 + q] * gp[q];
        sm[OFF_GOALC + r * TB + e] = s;
        sm[OFF_ABS + r * TB + e] = traj_abs[(size_t)(b0 + e) * 2 + r];
    }
    {
        int e = tid >> 1, p = tid & 1;
        float r0 = traj_rel[(size_t)(b0 + e) * 2 + 0];
        float r1 = traj_rel[(size_t)(b0 + e) * 2 + 1];
        #pragma unroll
        for (int i = 0; i < 8; i++) {
            int xi = p * 8 + i;
            float v = sm[OFF_WSE + xi * 2] * r0 + sm[OFF_WSE + xi * 2 + 1] * r1 + sm[OFF_BSE + xi];
            v = (v > 0.f) ? v : 0.01f * v;
            sm[OFF_A + (64 + xi) * TBP + e] = v;   // x rows of buffer 0
        }
    }
    __syncthreads();

    const int tx = tid & 15;   // gate group: j = gc*16 + tx
    const int ty = tid >> 4;   // element group
    const int e0 = ty * 8;

    for (int step = 0; step < SEQ; step++) {
        const int buf = step & 1;
        float* Abuf = sm + OFF_A + buf * 80 * TBP;
        float* An   = sm + OFF_A + (buf ^ 1) * 80 * TBP;

        #pragma unroll 1
        for (int gc = 0; gc < 4; gc++) {
            const int g0 = gc * 64 + tx * 4;
            u64 acc[4][4];
            {
                const float4 bv = *(const float4*)(sm + OFF_BC + g0);
                u64 bi = pack2(bv.x), bf = pack2(bv.y), bg = pack2(bv.z), bo = pack2(bv.w);
                #pragma unroll
                for (int p = 0; p < 4; p++) { acc[p][0] = bi; acc[p][1] = bf; acc[p][2] = bg; acc[p][3] = bo; }
            }
            const float* Wp = sm + OFF_W + g0;
            const float* Ap = Abuf + e0;
            #pragma unroll 4
            for (int k = 0; k < KDIM; k++) {
                float4 w = *(const float4*)(Wp + k * NG);
                u64 w0 = pack2(w.x), w1 = pack2(w.y), w2v = pack2(w.z), w3 = pack2(w.w);
                const ulonglong2* ap = (const ulonglong2*)(Ap + k * TBP);
                ulonglong2 aA = ap[0];
                ulonglong2 aB = ap[1];
                ffma2(acc[0][0], aA.x, w0); ffma2(acc[0][1], aA.x, w1); ffma2(acc[0][2], aA.x, w2v); ffma2(acc[0][3], aA.x, w3);
                ffma2(acc[1][0], aA.y, w0); ffma2(acc[1][1], aA.y, w1); ffma2(acc[1][2], aA.y, w2v); ffma2(acc[1][3], aA.y, w3);
                ffma2(acc[2][0], aB.x, w0); ffma2(acc[2][1], aB.x, w1); ffma2(acc[2][2], aB.x, w2v); ffma2(acc[2][3], aB.x, w3);
                ffma2(acc[3][0], aB.y, w0); ffma2(acc[3][1], aB.y, w1); ffma2(acc[3][2], aB.y, w2v); ffma2(acc[3][3], aB.y, w3);
            }
            // pointwise LSTM for (j = gc*16+tx, elems e0..e0+7)
            const int j = gc * 16 + tx;
            float* crow = sm + OFF_C + j * TBP + e0;
            float* hrow = An + j * TBP + e0;
            #pragma unroll
            for (int p = 0; p < 4; p++) {
                float2 iv = unpack2(acc[p][0]);
                float2 fv = unpack2(acc[p][1]);
                float2 gv = unpack2(acc[p][2]);
                float2 ov = unpack2(acc[p][3]);
                float c0v = crow[2 * p], c1v = crow[2 * p + 1];
                float cn0 = sigf(fv.x) * c0v + sigf(iv.x) * tanh_fast(gv.x);
                float cn1 = sigf(fv.y) * c1v + sigf(iv.y) * tanh_fast(gv.y);
                crow[2 * p]     = cn0;
                crow[2 * p + 1] = cn1;
                hrow[2 * p]     = sigf(ov.x) * tanh_fast(cn0);
                hrow[2 * p + 1] = sigf(ov.y) * tanh_fast(cn1);
            }
        }
        __syncthreads();

        // rel pass: thread (e, r)
        {
            int e = tid >> 1, r = tid & 1;
            float a0 = sm[OFF_ABS + e];
            float a1 = sm[OFF_ABS + TB + e];
            float s = sm[OFF_CV + r] + sm[OFF_GOALC + r * TB + e]
                    + sm[OFF_M2 + r * 2 + 0] * a0 + sm[OFF_M2 + r * 2 + 1] * a1;
            const float* w2p = sm + OFF_W2 + r * 64;
            const float* hb = An + e;
            #pragma unroll 8
            for (int j2 = 0; j2 < 64; j2++) s += w2p[j2] * hb[j2 * TBP];
            sm[OFF_REL + r * TB + e] = s;
            out[((size_t)step * B + b0 + e) * 2 + r] = s;
        }
        __syncthreads();

        // abs update + next x
        {
            int e = tid >> 1, p = tid & 1;
            float r0 = sm[OFF_REL + e];
            float r1 = sm[OFF_REL + TB + e];
            if (p == 0) sm[OFF_ABS + e] += r0;
            else        sm[OFF_ABS + TB + e] += r1;
            #pragma unroll
            for (int i = 0; i < 8; i++) {
                int xi = p * 8 + i;
                float v = sm[OFF_WSE + xi * 2] * r0 + sm[OFF_WSE + xi * 2 + 1] * r1 + sm[OFF_BSE + xi];
                v = (v > 0.f) ? v : 0.01f * v;
                An[(64 + xi) * TBP + e] = v;
            }
        }
        __syncthreads();
    }
}

// ============================================================================
extern "C" void kernel_launch(void* const* d_in, const int* in_sizes, int n_in,
                              void* d_out, int out_size)
{
    const float* traj_abs = (const float*)d_in[0];
    const float* traj_rel = (const float*)d_in[1];
    const float* h0       = (const float*)d_in[2];
    const float* c0       = (const float*)d_in[3];
    const float* goals    = (const float*)d_in[4];
    const float* W_ih     = (const float*)d_in[5];
    const float* W_hh     = (const float*)d_in[6];
    const float* b_ih     = (const float*)d_in[7];
    const float* b_hh     = (const float*)d_in[8];
    const float* W_se     = (const float*)d_in[9];
    const float* b_se     = (const float*)d_in[10];
    const float* W_h2p    = (const float*)d_in[11];
    const float* b_h2p    = (const float*)d_in[12];
    const float* W_goal   = (const float*)d_in[13];
    const float* b_goal   = (const float*)d_in[14];
    const float* W_abs    = (const float*)d_in[15];
    const float* b_abs    = (const float*)d_in[16];

    int B = in_sizes[2] / HDIM;   // h0 has B*64 elements

    cudaFuncSetAttribute(lstm_main, cudaFuncAttributeMaxDynamicSharedMemorySize, SMEM_BYTES);

    prep_kernel<<<1, NTHR>>>(W_ih, W_hh, b_ih, b_hh, W_h2p, b_h2p,
                             W_goal, b_goal, W_abs, b_abs);
    lstm_main<<<B / TB, NTHR, SMEM_BYTES>>>(traj_abs, traj_rel, h0, c0, goals,
                                            W_se, b_se, (float*)d_out, B);
}

// round 3
// speedup vs baseline: 1.9551x; 1.9551x over previous
#include <cuda_runtime.h>
#include <cuda_bf16.h>
#include <cstdint>

// GoalDecoderLSTM, B=131072, H=64, E=16, SEQ=30  — classic HMMA (mma.sync bf16) path.
// Per step: D[128 elems, 256 gates] = A[128,80] @ B[256,80]^T, 3-term bf16 split.
// Gate col order: n = jb*32 + t*8 + jj  (j = 8*jb + jj), so each lane's D fragment
// holds all 4 gates for its (row, j) pairs. Warp (mw 0..3, nw 0..1): rows 32mw..+32,
// j range 32nw..+32. B pre-packed in mma-fragment order (1 LDS.64 per fragment).
// A fragments load from double-buffered bf16x2 H image (rows padded to 44 words).

#define TB    128
#define SEQ   30
#define NTHR  256
#define HROW  44

// SMEM byte offsets
#define SM_BFRAG   0                        // 320 frags * 256B = 81920
#define SM_H       81920                    // 2 bufs * (Hhi 22528 + Hlo 22528)
#define HBUF_BYTES 45056
#define SM_F       (SM_H + 2*HBUF_BYTES)    // 172032
// float indices within sF
#define FI_BC    0      // 256
#define FI_W2P   256    // 128 (pairs per j)
#define FI_MG    384    // 128
#define FI_M2    512    // 4
#define FI_CV    516    // 2
#define FI_CG    518    // 2
#define FI_WSE4  520    // 32
#define FI_BSE2  552    // 16
#define FI_RELP  568    // 256
#define SF_FLOATS 824
#define SMEM_BYTES (SM_F + SF_FLOATS*4)     // 175328

typedef uint32_t u32;
typedef unsigned long long u64;

// ---- device staging (prep -> main) ----
__device__ __align__(16) u64 g_Bfrag[320 * 32];   // 81920 B
__device__ float g_bc[256];
__device__ float g_w2p[128];
__device__ float g_Mg[128];
__device__ float g_M2[4];
__device__ float g_cv[2];
__device__ float g_cg[2];
__device__ float g_wse4[32];
__device__ float g_bse2[16];

// ---- helpers ----
__device__ __forceinline__ u32 pack_bf16(float lo, float hi) {
    u32 r;
    asm("cvt.rn.bf16x2.f32 %0, %1, %2;" : "=r"(r) : "f"(hi), "f"(lo));
    return r;
}
__device__ __forceinline__ void bf16_split(float a, float b, u32& hi, u32& lo) {
    hi = pack_bf16(a, b);                       // a -> low half, b -> high half
    float ra = a - __uint_as_float(hi << 16);
    float rb = b - __uint_as_float(hi & 0xFFFF0000u);
    lo = pack_bf16(ra, rb);
}
__device__ __forceinline__ void mma16816(float* d, const u32* a, u32 b0, u32 b1) {
    asm volatile("mma.sync.aligned.m16n8k16.row.col.f32.bf16.bf16.f32 "
        "{%0,%1,%2,%3}, {%4,%5,%6,%7}, {%8,%9}, {%0,%1,%2,%3};"
        : "+f"(d[0]), "+f"(d[1]), "+f"(d[2]), "+f"(d[3])
        : "r"(a[0]), "r"(a[1]), "r"(a[2]), "r"(a[3]), "r"(b0), "r"(b1));
}
__device__ __forceinline__ float sigf(float x) {
    return __fdividef(1.0f, 1.0f + __expf(-x));
}
__device__ __forceinline__ float tanh_fast(float x) {
    float ax = fabsf(x);
    float e  = __expf(-2.0f * ax);
    float t  = __fdividef(1.0f - e, 1.0f + e);
    return copysignf(t, x);
}

// ============================================================================
// Prep: fold small matrices; build B in mma-fragment order (bf16 hi/lo)
// ============================================================================
__global__ void prep_kernel(const float* __restrict__ W_ih, const float* __restrict__ W_hh,
                            const float* __restrict__ b_ih, const float* __restrict__ b_hh,
                            const float* __restrict__ W_h2p, const float* __restrict__ b_h2p,
                            const float* __restrict__ W_goal, const float* __restrict__ b_goal,
                            const float* __restrict__ W_abs, const float* __restrict__ b_abs,
                            const float* __restrict__ W_se, const float* __restrict__ b_se)
{
    int tid = threadIdx.x;
    // frag f = (((img*2+nw)*4+g)*5+kc)*4+t, lane l
    for (int idx = tid; idx < 320 * 32; idx += NTHR) {
        int f = idx >> 5, l = idx & 31;
        int t = f & 3, kc = (f >> 2) % 5, g = (f / 20) & 3, nw = (f / 80) & 1, img = f / 160;
        int jj = l >> 2, c4 = l & 3;
        int j = 32 * nw + 8 * g + jj;
        int row = t * 64 + j;
        int k0 = 16 * kc + 2 * c4;
        float v[4];
        #pragma unroll
        for (int i = 0; i < 4; i++) {
            int k = k0 + (i & 1) + (i >> 1) * 8;
            v[i] = (k < 64) ? W_hh[row * 64 + k] : W_ih[row * 16 + (k - 64)];
        }
        u32 w0, w1;
        if (img == 0) {
            __nv_bfloat16 a = __float2bfloat16(v[0]), b = __float2bfloat16(v[1]);
            __nv_bfloat16 c = __float2bfloat16(v[2]), d = __float2bfloat16(v[3]);
            w0 = (u32)*(uint16_t*)&a | ((u32)*(uint16_t*)&b << 16);
            w1 = (u32)*(uint16_t*)&c | ((u32)*(uint16_t*)&d << 16);
        } else {
            float r[4];
            #pragma unroll
            for (int i = 0; i < 4; i++) {
                __nv_bfloat16 h = __float2bfloat16(v[i]);
                r[i] = v[i] - __bfloat162float(h);
            }
            __nv_bfloat16 a = __float2bfloat16(r[0]), b = __float2bfloat16(r[1]);
            __nv_bfloat16 c = __float2bfloat16(r[2]), d = __float2bfloat16(r[3]);
            w0 = (u32)*(uint16_t*)&a | ((u32)*(uint16_t*)&b << 16);
            w1 = (u32)*(uint16_t*)&c | ((u32)*(uint16_t*)&d << 16);
        }
        g_Bfrag[idx] = (u64)w0 | ((u64)w1 << 32);
    }
    {
        int j = tid & 63, t = tid >> 6, row = t * 64 + j;
        g_bc[tid] = b_ih[row] + b_hh[row];
    }
    if (tid < 64) {
        g_w2p[2 * tid]     = W_h2p[tid];            // W2[0][j]
        g_w2p[2 * tid + 1] = W_h2p[192 + tid];      // W2[1][j]
    }
    if (tid < 128) {
        int r = tid >> 6, j = tid & 63;
        float s = 0.f;
        for (int m = 0; m < 64; m++) s += W_h2p[r * 192 + 128 + m] * W_goal[m * 64 + j];
        g_Mg[tid] = s;
    }
    if (tid < 4) {
        int r = tid >> 1, c = tid & 1;
        float s = 0.f;
        for (int m = 0; m < 64; m++) s += W_h2p[r * 192 + 64 + m] * W_abs[m * 2 + c];
        g_M2[tid] = s;
    }
    if (tid < 2) {
        float s = b_h2p[tid];
        for (int m = 0; m < 64; m++) s += W_h2p[tid * 192 + 64 + m] * b_abs[m];
        g_cv[tid] = s;
        float s2 = 0.f;
        for (int m = 0; m < 64; m++) s2 += W_h2p[tid * 192 + 128 + m] * b_goal[m];
        g_cg[tid] = s2;
    }
    if (tid < 8) {
        g_wse4[tid * 4 + 0] = W_se[(2 * tid) * 2 + 0];
        g_wse4[tid * 4 + 1] = W_se[(2 * tid) * 2 + 1];
        g_wse4[tid * 4 + 2] = W_se[(2 * tid + 1) * 2 + 0];
        g_wse4[tid * 4 + 3] = W_se[(2 * tid + 1) * 2 + 1];
        g_bse2[tid * 2 + 0] = b_se[2 * tid];
        g_bse2[tid * 2 + 1] = b_se[2 * tid + 1];
    }
}

// ============================================================================
// Main kernel
// ============================================================================
__global__ void __launch_bounds__(NTHR, 1)
lstm_main(const float* __restrict__ traj_abs, const float* __restrict__ traj_rel,
          const float* __restrict__ h0g, const float* __restrict__ c0g,
          const float* __restrict__ goals, float* __restrict__ out, int Btot)
{
    extern __shared__ __align__(16) char smem[];
    float* sF = (float*)(smem + SM_F);
    const int tid = threadIdx.x, l = tid & 31, wid = tid >> 5;
    const int mw = wid & 3, nw = wid >> 2;
    const int c4 = l & 3, q = l >> 2;
    const int b0 = blockIdx.x * TB;

    // ---- copy staged weights into SMEM ----
    {
        const float4* src = (const float4*)g_Bfrag;
        float4* dst = (float4*)(smem + SM_BFRAG);
        for (int i = tid; i < 5120; i += NTHR) dst[i] = src[i];
    }
    for (int i = tid; i < 256; i += NTHR) sF[FI_BC + i] = g_bc[i];
    for (int i = tid; i < 128; i += NTHR) { sF[FI_W2P + i] = g_w2p[i]; sF[FI_MG + i] = g_Mg[i]; }
    if (tid < 4)  sF[FI_M2 + tid] = g_M2[tid];
    if (tid < 2)  { sF[FI_CV + tid] = g_cv[tid]; sF[FI_CG + tid] = g_cg[tid]; }
    if (tid < 32) sF[FI_WSE4 + tid] = g_wse4[tid];
    if (tid < 16) sF[FI_BSE2 + tid] = g_bse2[tid];
    __syncthreads();

    // ---- init H buffer 0 from h0, x0 ----
    {
        u32* Hhi = (u32*)(smem + SM_H);
        u32* Hlo = (u32*)(smem + SM_H + 22528);
        for (int idx = tid; idx < 128 * 40; idx += NTHR) {
            int row = idx / 40, w = idx - row * 40;
            float2 hv = *(const float2*)(h0g + (size_t)(b0 + row) * 64 + 2 * w);
            u32 hw, lw; bf16_split(hv.x, hv.y, hw, lw);
            Hhi[row * HROW + w] = hw; Hlo[row * HROW + w] = lw;
        }
        for (int idx = tid; idx < 128 * 8; idx += NTHR) {
            int row = idx >> 3, p = idx & 7;
            float2 tr = *(const float2*)(traj_rel + (size_t)(b0 + row) * 2);
            float4 w4 = *(const float4*)(sF + FI_WSE4 + 4 * p);
            float xa = w4.x * tr.x + w4.y * tr.y + sF[FI_BSE2 + 2 * p];
            float xb = w4.z * tr.x + w4.w * tr.y + sF[FI_BSE2 + 2 * p + 1];
            xa = (xa > 0.f) ? xa : 0.01f * xa;
            xb = (xb > 0.f) ? xb : 0.01f * xb;
            u32 hw, lw; bf16_split(xa, xb, hw, lw);
            Hhi[row * HROW + 32 + p] = hw; Hlo[row * HROW + 32 + p] = lw;
        }
    }

    // ---- c-state into registers: creg[g][m][rh][jj] ----
    float creg[4][2][2][2];
    #pragma unroll
    for (int g = 0; g < 4; g++)
        #pragma unroll
        for (int m = 0; m < 2; m++)
            #pragma unroll
            for (int rh = 0; rh < 2; rh++) {
                int row = 32 * mw + 16 * m + 8 * rh + q;
                int j = 32 * nw + 8 * g + 2 * c4;
                float2 cv2 = *(const float2*)(c0g + (size_t)(b0 + row) * 64 + j);
                creg[g][m][rh][0] = cv2.x; creg[g][m][rh][1] = cv2.y;
            }

    // ---- per-row derived state (nw==0 warps own it) ----
    float goc[4][2], ab[4][2];
    if (nw == 0) {
        #pragma unroll
        for (int m = 0; m < 2; m++)
            #pragma unroll
            for (int rh = 0; rh < 2; rh++) {
                int rl = 2 * m + rh;
                int row = 32 * mw + 16 * m + 8 * rh + q;
                ab[rl][0] = traj_abs[(size_t)(b0 + row) * 2];
                ab[rl][1] = traj_abs[(size_t)(b0 + row) * 2 + 1];
                float s0 = sF[FI_CG], s1 = sF[FI_CG + 1];
                const float* gp = goals + (size_t)(b0 + row) * 64;
                #pragma unroll 8
                for (int k = 0; k < 64; k++) {
                    float gv = gp[k];
                    s0 += sF[FI_MG + k] * gv;
                    s1 += sF[FI_MG + 64 + k] * gv;
                }
                goc[rl][0] = s0; goc[rl][1] = s1;
            }
    }
    __syncthreads();

    const u64* BfragS = (const u64*)(smem + SM_BFRAG);

    for (int s = 0; s < SEQ; s++) {
        const u32* Hhi = (const u32*)(smem + SM_H + (s & 1) * HBUF_BYTES);
        const u32* Hlo = Hhi + 5632;
        u32* Nhi = (u32*)(smem + SM_H + ((s + 1) & 1) * HBUF_BYTES);
        u32* Nlo = Nhi + 5632;

        // ---- load A fragments (hi/lo) ----
        u32 Ahi[2][5][4], Alo[2][5][4];
        #pragma unroll
        for (int m = 0; m < 2; m++) {
            const int rbase = (32 * mw + 16 * m + q) * HROW;
            #pragma unroll
            for (int kc = 0; kc < 5; kc++) {
                int w0 = 8 * kc + c4, w1 = w0 + 4;
                Ahi[m][kc][0] = Hhi[rbase + w0];
                Ahi[m][kc][1] = Hhi[rbase + 8 * HROW + w0];
                Ahi[m][kc][2] = Hhi[rbase + w1];
                Ahi[m][kc][3] = Hhi[rbase + 8 * HROW + w1];
                Alo[m][kc][0] = Hlo[rbase + w0];
                Alo[m][kc][1] = Hlo[rbase + 8 * HROW + w0];
                Alo[m][kc][2] = Hlo[rbase + w1];
                Alo[m][kc][3] = Hlo[rbase + 8 * HROW + w1];
            }
        }

        float rp[4][2] = {};
        #pragma unroll
        for (int g = 0; g < 4; g++) {
            float acc[2][4][4] = {};
            #pragma unroll
            for (int kc = 0; kc < 5; kc++) {
                #pragma unroll
                for (int t = 0; t < 4; t++) {
                    u64 bh = BfragS[(u32)((((0 + nw) * 4 + g) * 5 + kc) * 4 + t) * 32 + l];
                    u64 bl = BfragS[(u32)((((2 + nw) * 4 + g) * 5 + kc) * 4 + t) * 32 + l];
                    u32 bh0 = (u32)bh, bh1 = (u32)(bh >> 32);
                    u32 bl0 = (u32)bl, bl1 = (u32)(bl >> 32);
                    #pragma unroll
                    for (int m = 0; m < 2; m++) {
                        mma16816(acc[m][t], Ahi[m][kc], bh0, bh1);
                        mma16816(acc[m][t], Alo[m][kc], bh0, bh1);
                        mma16816(acc[m][t], Ahi[m][kc], bl0, bl1);
                    }
                }
            }
            // ---- epilogue for group g ----
            const int jbase = 32 * nw + 8 * g + 2 * c4;
            const float2 bI = *(const float2*)(sF + FI_BC + jbase);
            const float2 bF = *(const float2*)(sF + FI_BC + 64 + jbase);
            const float2 bG = *(const float2*)(sF + FI_BC + 128 + jbase);
            const float2 bO = *(const float2*)(sF + FI_BC + 192 + jbase);
            const float4 w2q = *(const float4*)(sF + FI_W2P + 2 * jbase);
            const int wcol = 16 * nw + 4 * g + c4;
            #pragma unroll
            for (int m = 0; m < 2; m++) {
                #pragma unroll
                for (int rh = 0; rh < 2; rh++) {
                    const int rl = 2 * m + rh;
                    float iv0 = acc[m][0][2 * rh] + bI.x, iv1 = acc[m][0][2 * rh + 1] + bI.y;
                    float fv0 = acc[m][1][2 * rh] + bF.x, fv1 = acc[m][1][2 * rh + 1] + bF.y;
                    float gv0 = acc[m][2][2 * rh] + bG.x, gv1 = acc[m][2][2 * rh + 1] + bG.y;
                    float ov0 = acc[m][3][2 * rh] + bO.x, ov1 = acc[m][3][2 * rh + 1] + bO.y;
                    float cn0 = sigf(fv0) * creg[g][m][rh][0] + sigf(iv0) * tanh_fast(gv0);
                    float cn1 = sigf(fv1) * creg[g][m][rh][1] + sigf(iv1) * tanh_fast(gv1);
                    creg[g][m][rh][0] = cn0; creg[g][m][rh][1] = cn1;
                    float h0v = sigf(ov0) * tanh_fast(cn0);
                    float h1v = sigf(ov1) * tanh_fast(cn1);
                    rp[rl][0] += w2q.x * h0v + w2q.z * h1v;
                    rp[rl][1] += w2q.y * h0v + w2q.w * h1v;
                    u32 hw, lw; bf16_split(h0v, h1v, hw, lw);
                    const int row = 32 * mw + 16 * m + 8 * rh + q;
                    Nhi[row * HROW + wcol] = hw;
                    Nlo[row * HROW + wcol] = lw;
                }
            }
        }

        // ---- rel reduction: butterfly over the 4 lanes of each quad ----
        #pragma unroll
        for (int rl = 0; rl < 4; rl++) {
            #pragma unroll
            for (int ax = 0; ax < 2; ax++) {
                float v = rp[rl][ax];
                v += __shfl_xor_sync(0xFFFFFFFFu, v, 1);
                v += __shfl_xor_sync(0xFFFFFFFFu, v, 2);
                rp[rl][ax] = v;
            }
        }
        if (nw == 1 && c4 == 0) {
            #pragma unroll
            for (int rl = 0; rl < 4; rl++) {
                int row = 32 * mw + 16 * (rl >> 1) + 8 * (rl & 1) + q;
                *(float2*)(sF + FI_RELP + 2 * row) = make_float2(rp[rl][0], rp[rl][1]);
            }
        }
        __syncthreads();

        if (nw == 0) {
            #pragma unroll
            for (int rl = 0; rl < 4; rl++) {
                const int row = 32 * mw + 16 * (rl >> 1) + 8 * (rl & 1) + q;
                float2 pt = *(const float2*)(sF + FI_RELP + 2 * row);
                float r0 = rp[rl][0] + pt.x + sF[FI_CV] + goc[rl][0]
                         + sF[FI_M2] * ab[rl][0] + sF[FI_M2 + 1] * ab[rl][1];
                float r1 = rp[rl][1] + pt.y + sF[FI_CV + 1] + goc[rl][1]
                         + sF[FI_M2 + 2] * ab[rl][0] + sF[FI_M2 + 3] * ab[rl][1];
                if (c4 == 0)
                    *(float2*)(out + ((size_t)s * Btot + b0 + row) * 2) = make_float2(r0, r1);
                ab[rl][0] += r0; ab[rl][1] += r1;
                if (s < SEQ - 1) {
                    #pragma unroll
                    for (int pi = 0; pi < 2; pi++) {
                        int p = c4 + 4 * pi;
                        float4 w4 = *(const float4*)(sF + FI_WSE4 + 4 * p);
                        float xa = w4.x * r0 + w4.y * r1 + sF[FI_BSE2 + 2 * p];
                        float xb = w4.z * r0 + w4.w * r1 + sF[FI_BSE2 + 2 * p + 1];
                        xa = (xa > 0.f) ? xa : 0.01f * xa;
                        xb = (xb > 0.f) ? xb : 0.01f * xb;
                        u32 hw, lw; bf16_split(xa, xb, hw, lw);
                        Nhi[row * HROW + 32 + p] = hw;
                        Nlo[row * HROW + 32 + p] = lw;
                    }
                }
            }
        }
        __syncthreads();
    }
}

// ============================================================================
extern "C" void kernel_launch(void* const* d_in, const int* in_sizes, int n_in,
                              void* d_out, int out_size)
{
    const float* traj_abs = (const float*)d_in[0];
    const float* traj_rel = (const float*)d_in[1];
    const float* h0       = (const float*)d_in[2];
    const float* c0       = (const float*)d_in[3];
    const float* goals    = (const float*)d_in[4];
    const float* W_ih     = (const float*)d_in[5];
    const float* W_hh     = (const float*)d_in[6];
    const float* b_ih     = (const float*)d_in[7];
    const float* b_hh     = (const float*)d_in[8];
    const float* W_se     = (const float*)d_in[9];
    const float* b_se     = (const float*)d_in[10];
    const float* W_h2p    = (const float*)d_in[11];
    const float* b_h2p    = (const float*)d_in[12];
    const float* W_goal   = (const float*)d_in[13];
    const float* b_goal   = (const float*)d_in[14];
    const float* W_abs    = (const float*)d_in[15];
    const float* b_abs    = (const float*)d_in[16];

    int B = in_sizes[2] / 64;

    cudaFuncSetAttribute(lstm_main, cudaFuncAttributeMaxDynamicSharedMemorySize, SMEM_BYTES);

    prep_kernel<<<1, NTHR>>>(W_ih, W_hh, b_ih, b_hh, W_h2p, b_h2p,
                             W_goal, b_goal, W_abs, b_abs, W_se, b_se);
    lstm_main<<<B / TB, NTHR, SMEM_BYTES>>>(traj_abs, traj_rel, h0, c0, goals,
                                            (float*)d_out, B);
}